// round 1
// baseline (speedup 1.0000x reference)
#include <cuda_runtime.h>
#include <stdint.h>

// AE_spikes: spiking autoencoder, B=16384, 784 -> 128 -> 128 -> 128 -> 784, T=16.
// Key decomposition: per-layer recurrences are independent over time given the
// full spike trains of the previous layer. Spike trains stored as u16 bitmasks
// (bit t = spike at step t). Five kernels: encoder, 3 hidden layers, output layer.

#define BATCH  16384
#define INF    784
#define HID    128
#define TSTEPS 16

// Scratch (device globals -- no allocation allowed in kernel_launch)
__device__ uint16_t g_S0[BATCH * INF];   // encoder spikes   [B][784]
__device__ uint16_t g_S1[BATCH * HID];   // layer1 spikes    [B][128]
__device__ uint16_t g_S2[BATCH * HID];
__device__ uint16_t g_S3[BATCH * HID];

// ---------------------------------------------------------------------------
// Encoder: v += f; spike if v >= 1; v -= spike.  Bit-exact vs reference
// (same sequential fp32 adds, elementwise).
// ---------------------------------------------------------------------------
__global__ void __launch_bounds__(256) enc_kernel(const float* __restrict__ f) {
    int idx = blockIdx.x * blockDim.x + threadIdx.x;
    if (idx >= BATCH * INF) return;
    float x = f[idx];
    float v = 0.0f;
    unsigned m = 0;
#pragma unroll
    for (int t = 0; t < TSTEPS; t++) {
        v += x;
        if (v >= 1.0f) { m |= (1u << t); v -= 1.0f; }
    }
    g_S0[idx] = (uint16_t)m;
}

// ---------------------------------------------------------------------------
// Hidden layer (emits spike bitmasks):
//   per (b, j): acc[t] = sum_i Sin[b,i,t] * W[j,i]   (predicated adds)
//   then v = (v + acc[t]) + bias[j]; spike; reset-by-subtraction.
// Block = BTILE batch rows x JG output groups. Input masks staged in smem,
// transposed to [K][BTILE] so a warp's mask reads are conflict-free broadcasts.
// ---------------------------------------------------------------------------
template <int K, int BTILE, int JG, int NOUT>
__global__ void __launch_bounds__(BTILE * JG) layer_mask_kernel(
    const uint16_t* __restrict__ Sin, const float* __restrict__ W,
    const float* __restrict__ bias, uint16_t* __restrict__ Sout)
{
    __shared__ uint16_t sm[K][BTILE];
    const int tid = threadIdx.x;
    const int b0  = blockIdx.x * BTILE;

    for (int idx = tid; idx < K * BTILE; idx += BTILE * JG) {
        int i  = idx % K;          // coalesced gmem read (i fast)
        int bl = idx / K;
        sm[i][bl] = Sin[(b0 + bl) * K + i];
    }
    __syncthreads();

    const int bl = tid % BTILE;
    const int jg = tid / BTILE;
    const int b  = b0 + bl;

#pragma unroll 1
    for (int p = 0; p < NOUT / JG; p++) {
        const int j = jg + JG * p;
        const float* wr = W + j * K;
        float acc[TSTEPS];
#pragma unroll
        for (int t = 0; t < TSTEPS; t++) acc[t] = 0.0f;

#pragma unroll 4
        for (int i = 0; i < K; i++) {
            float    w = __ldg(wr + i);
            unsigned m = sm[i][bl];
#pragma unroll
            for (int t = 0; t < TSTEPS; t++)
                if (m & (1u << t)) acc[t] += w;   // LOP3.pred + @P FADD
        }

        const float bj = __ldg(bias + j);
        float v = 0.0f;
        unsigned om = 0;
#pragma unroll
        for (int t = 0; t < TSTEPS; t++) {
            v = (v + acc[t]) + bj;                // match ref order: (v + z) + b
            if (v >= 1.0f) { om |= (1u << t); v -= 1.0f; }
        }
        Sout[b * NOUT + j] = (uint16_t)om;
    }
}

// ---------------------------------------------------------------------------
// Output layer: same inner structure, K=128, 784 outputs; counts spikes and
// writes firing rate = count / 16.
// ---------------------------------------------------------------------------
__global__ void __launch_bounds__(256) layer4_kernel(
    const uint16_t* __restrict__ Sin, const float* __restrict__ W,
    const float* __restrict__ bias, float* __restrict__ out)
{
    __shared__ uint16_t sm[HID][32];
    const int tid = threadIdx.x;
    const int b0  = blockIdx.x * 32;

    for (int idx = tid; idx < HID * 32; idx += 256) {
        int i  = idx % HID;
        int bl = idx / HID;
        sm[i][bl] = Sin[(b0 + bl) * HID + i];
    }
    __syncthreads();

    const int bl = tid % 32;   // warp = 32 consecutive batch rows
    const int og = tid / 32;   // 8 output groups
    const int b  = b0 + bl;

#pragma unroll 1
    for (int p = 0; p < INF / 8; p++) {
        const int o = og + 8 * p;
        const float* wr = W + o * HID;
        float acc[TSTEPS];
#pragma unroll
        for (int t = 0; t < TSTEPS; t++) acc[t] = 0.0f;

#pragma unroll 4
        for (int k = 0; k < HID; k++) {
            float    w = __ldg(wr + k);
            unsigned m = sm[k][bl];
#pragma unroll
            for (int t = 0; t < TSTEPS; t++)
                if (m & (1u << t)) acc[t] += w;
        }

        const float bo = __ldg(bias + o);
        float v = 0.0f, cnt = 0.0f;
#pragma unroll
        for (int t = 0; t < TSTEPS; t++) {
            v = (v + acc[t]) + bo;
            if (v >= 1.0f) { cnt += 1.0f; v -= 1.0f; }
        }
        out[b * INF + o] = cnt * 0.0625f;   // /16 exact
    }
}

// ---------------------------------------------------------------------------
extern "C" void kernel_launch(void* const* d_in, const int* in_sizes, int n_in,
                              void* d_out, int out_size)
{
    const float* features = (const float*)d_in[0];
    const float* W1 = (const float*)d_in[1];
    const float* b1 = (const float*)d_in[2];
    const float* W2 = (const float*)d_in[3];
    const float* b2 = (const float*)d_in[4];
    const float* W3 = (const float*)d_in[5];
    const float* b3 = (const float*)d_in[6];
    const float* W4 = (const float*)d_in[7];
    const float* b4 = (const float*)d_in[8];
    float* out = (float*)d_out;

    uint16_t *s0, *s1, *s2, *s3;
    cudaGetSymbolAddress((void**)&s0, g_S0);
    cudaGetSymbolAddress((void**)&s1, g_S1);
    cudaGetSymbolAddress((void**)&s2, g_S2);
    cudaGetSymbolAddress((void**)&s3, g_S3);

    enc_kernel<<<(BATCH * INF + 255) / 256, 256>>>(features);
    layer_mask_kernel<INF, 16, 16, HID><<<BATCH / 16, 256>>>(s0, W1, b1, s1);
    layer_mask_kernel<HID, 32,  8, HID><<<BATCH / 32, 256>>>(s1, W2, b2, s2);
    layer_mask_kernel<HID, 32,  8, HID><<<BATCH / 32, 256>>>(s2, W3, b3, s3);
    layer4_kernel<<<BATCH / 32, 256>>>(s3, W4, b4, out);
}

// round 4
// speedup vs baseline: 3.7670x; 3.7670x over previous
#include <cuda_runtime.h>
#include <stdint.h>

// AE_spikes via mma.sync s8 tensor cores (sm_100 base target).
// Layers = GEMM over rows (t,b). Binary spikes exact in s8. Weights as 3 s8
// limbs, base 254, per-row scale: w ~= s0*(q0 + q1/254 + q2/64516), residual
// <= 6e-8*rowmax. Per-limb int32 accumulators persist across K panels (exact
// integer sums; limbs combined once at the end: s0*D0 + (s0/64516)*(254*D1+D2)).
// Fire-and-reset scan fused in epilogue via smem.

#define BATCH  16384
#define TSTEPS 16
#define KP1    896        // 784 padded to 7*128

// ---------------- scratch ----------------
__device__ uint16_t g_M0[BATCH * KP1];
__device__ uint16_t g_M1[BATCH * 128];
__device__ uint16_t g_M2[BATCH * 128];
__device__ uint16_t g_M3[BATCH * 128];
__device__ int8_t   g_Q1[3 * 128 * KP1];
__device__ int8_t   g_Q2[3 * 128 * 128];
__device__ int8_t   g_Q3[3 * 128 * 128];
__device__ int8_t   g_Q4[3 * 784 * 128];
__device__ float    g_S1[128], g_S2[128], g_S3[128], g_S4[784];

// ---------------- helpers ----------------
__device__ __forceinline__ uint32_t smem_u32(const void* p) {
    uint32_t a;
    asm("{ .reg .u64 t; cvta.to.shared.u64 t, %1; cvt.u32.u64 %0, t; }"
        : "=r"(a) : "l"(p));
    return a;
}
__device__ __forceinline__ void mma8(int* d, const uint32_t* a, uint32_t b0, uint32_t b1) {
    asm volatile(
        "mma.sync.aligned.m16n8k32.row.col.s32.s8.s8.s32 "
        "{%0,%1,%2,%3}, {%4,%5,%6,%7}, {%8,%9}, {%0,%1,%2,%3};"
        : "+r"(d[0]), "+r"(d[1]), "+r"(d[2]), "+r"(d[3])
        : "r"(a[0]), "r"(a[1]), "r"(a[2]), "r"(a[3]), "r"(b0), "r"(b1));
}
__device__ __forceinline__ void cpa16(uint32_t dst, const void* src, uint32_t ssz) {
    asm volatile("cp.async.cg.shared.global [%0], [%1], 16, %2;"
                 :: "r"(dst), "l"(src), "r"(ssz));
}

// ---------------- encoder ----------------
__global__ void __launch_bounds__(256) enc_kernel(const float* __restrict__ f) {
    int idx = blockIdx.x * blockDim.x + threadIdx.x;
    if (idx >= BATCH * KP1) return;
    int b = idx / KP1, i = idx - b * KP1;
    unsigned m = 0;
    if (i < 784) {
        float x = f[b * 784 + i], v = 0.0f;
#pragma unroll
        for (int t = 0; t < TSTEPS; t++) {
            v += x;
            if (v >= 1.0f) { m |= (1u << t); v -= 1.0f; }
        }
    }
    g_M0[idx] = (uint16_t)m;
}

// ---------------- weight 3-limb s8 split, base 254, double precision -------
__global__ void __launch_bounds__(32) wsplit(const float* __restrict__ W,
                                             int8_t* __restrict__ Q,
                                             float* __restrict__ S,
                                             int N, int K, int KP)
{
    int j = blockIdx.x, lane = threadIdx.x;
    const float* w = W + (size_t)j * K;
    float m = 0.0f;
    for (int k = lane; k < K; k += 32) m = fmaxf(m, fabsf(w[k]));
#pragma unroll
    for (int o = 16; o; o >>= 1) m = fmaxf(m, __shfl_xor_sync(~0u, m, o));
    float s0 = (m > 0.0f) ? m / 127.0f : 1.0f;
    if (lane == 0) S[j] = s0;
    double s0d = (double)s0;
    for (int k = lane; k < KP; k += 32) {
        double q0 = 0.0, q1 = 0.0, q2 = 0.0;
        if (k < K) {
            double wd = (double)w[k];
            q0 = fmin(fmax(rint(wd / s0d), -127.0), 127.0);
            double r1 = wd - q0 * s0d;
            q1 = fmin(fmax(rint(r1 * 254.0 / s0d), -127.0), 127.0);
            double r2 = r1 - q1 * s0d / 254.0;
            q2 = fmin(fmax(rint(r2 * 64516.0 / s0d), -127.0), 127.0);
        }
        size_t base = (size_t)j * KP + k, lstr = (size_t)N * KP;
        Q[base]            = (int8_t)(int)q0;
        Q[base + lstr]     = (int8_t)(int)q1;
        Q[base + 2 * lstr] = (int8_t)(int)q2;
    }
}

// ---------------- fused s8-GEMM + spiking scan ----------------
// grid: (BATCH/8, ceil(NOUT/64)); 256 threads (8 warps).
// CTA tile: M=128 rows (8 b x 16 t, t fastest) x N=64. Warp tile 16x64.
template <int KP, int NOUT, bool IS_LAST>
__global__ void __launch_bounds__(256, 2) gemm_spike(
    const uint16_t* __restrict__ Min, const int8_t* __restrict__ Wq,
    const float* __restrict__ Sc, const float* __restrict__ bias,
    uint16_t* __restrict__ Mout, float* __restrict__ Out)
{
    extern __shared__ __align__(16) char sm[];
    constexpr int NPAN   = KP / 128;
    constexpr int MSK_B  = 8 * KP * 2;
    constexpr int OFF_A  = MSK_B;                 // 128 rows x pitch 144 s8
    constexpr int OFF_B  = OFF_A + 128 * 144;     // 2 bufs x 3 limbs x 64 x 144
    constexpr int OFF_SC = OFF_B + 2 * 3 * 64 * 144;
    constexpr int OFF_C  = OFF_A;                 // scan buf reuses A+B region
    constexpr int BBUF   = 3 * 64 * 144;          // 27648

    const uint32_t sbase = smem_u32(sm);
    const int tid  = threadIdx.x;
    const int lane = tid & 31, wm = tid >> 5;
    const int g = lane >> 2, tg = lane & 3;
    const int b0 = blockIdx.x * 8;
    const int n0 = blockIdx.y * 64;

    // stage masks (8 rows contiguous in gmem)
    {
        const uint4* msrc = (const uint4*)(Min + (size_t)b0 * KP);
        uint4* mdst = (uint4*)sm;
        for (int u = tid; u < MSK_B / 16; u += 256) mdst[u] = msrc[u];
    }
    // stage scales / bias
    if (tid < 64) {
        int j = n0 + tid;
        float s = (j < NOUT) ? Sc[j] : 0.0f;
        ((float*)(sm + OFF_SC))[tid]       = s;
        ((float*)(sm + OFF_SC))[64 + tid]  = s * (1.0f / 64516.0f);
        ((float*)(sm + OFF_SC))[128 + tid] = (j < NOUT) ? bias[j] : 0.0f;
    }
    // issue B panel 0
    auto loadB = [&](int p, int buf) {
        const int bk = p * 128;
        for (int v = tid; v < 1536; v += 256) {
            int l = v >> 9, rem = v & 511, r = rem >> 3, cs = rem & 7;
            int row = n0 + r;
            uint32_t ssz = (row < NOUT) ? 16u : 0u;
            int rc = row < NOUT ? row : 0;
            const int8_t* src = Wq + ((size_t)l * NOUT + rc) * KP + bk + cs * 16;
            cpa16(sbase + OFF_B + buf * BBUF + l * 9216 + r * 144 + cs * 16, src, ssz);
        }
        asm volatile("cp.async.commit_group;");
    };
    loadB(0, 0);
    __syncthreads();   // masks visible

    int D0[8][4], D1[8][4], D2[8][4];
#pragma unroll
    for (int ni = 0; ni < 8; ni++)
#pragma unroll
        for (int r = 0; r < 4; r++) { D0[ni][r] = 0; D1[ni][r] = 0; D2[ni][r] = 0; }

#pragma unroll 1
    for (int p = 0; p < NPAN; p++) {
        const int buf = p & 1;
        // expand A panel: bitmask bit t -> s8 rows [bl*16+t][kq*4..+3]
        {
            const uint64_t* m64 = (const uint64_t*)sm;
            int bl = tid >> 5, kq = tid & 31;
            uint64_t mv = m64[bl * (KP / 4) + p * 32 + kq];
            uint32_t lo = (uint32_t)mv, hi = (uint32_t)(mv >> 32);
            char* arow = sm + OFF_A + (bl * 16) * 144 + kq * 4;
#pragma unroll
            for (int t = 0; t < 16; t++) {
                uint32_t xl = (lo >> t) & 0x00010001u; xl |= xl >> 15;
                uint32_t xh = (hi >> t) & 0x00010001u; xh |= xh >> 15;
                uint32_t nib = (xl & 3u) | ((xh & 3u) << 2);
                *(uint32_t*)(arow + t * 144) = (nib * 0x00204081u) & 0x01010101u;
            }
        }
        if (p + 1 < NPAN) {
            loadB(p + 1, buf ^ 1);
            asm volatile("cp.async.wait_group 1;");
        } else {
            asm volatile("cp.async.wait_group 0;");
        }
        __syncthreads();

#pragma unroll
        for (int ch = 0; ch < 4; ch++) {
            uint32_t afr[4];
            const char* ab = sm + OFF_A + (wm * 16) * 144 + ch * 32;
            afr[0] = *(const uint32_t*)(ab + g * 144 + tg * 4);
            afr[1] = *(const uint32_t*)(ab + (g + 8) * 144 + tg * 4);
            afr[2] = *(const uint32_t*)(ab + g * 144 + 16 + tg * 4);
            afr[3] = *(const uint32_t*)(ab + (g + 8) * 144 + 16 + tg * 4);
#pragma unroll
            for (int ni = 0; ni < 8; ni++) {
                const char* bb = sm + OFF_B + buf * BBUF + (ni * 8 + g) * 144 + ch * 32;
                uint32_t b00 = *(const uint32_t*)(bb + tg * 4);
                uint32_t b01 = *(const uint32_t*)(bb + 16 + tg * 4);
                uint32_t b10 = *(const uint32_t*)(bb + 9216 + tg * 4);
                uint32_t b11 = *(const uint32_t*)(bb + 9216 + 16 + tg * 4);
                uint32_t b20 = *(const uint32_t*)(bb + 18432 + tg * 4);
                uint32_t b21 = *(const uint32_t*)(bb + 18432 + 16 + tg * 4);
                mma8(D0[ni], afr, b00, b01);
                mma8(D1[ni], afr, b10, b11);
                mma8(D2[ni], afr, b20, b21);
            }
        }
        __syncthreads();   // A / B-buf reuse barrier
    }

    // combine limbs exactly and store to scan buffer
    float* cs = (float*)(sm + OFF_C);
    const float* s0a  = (const float*)(sm + OFF_SC);
    const float* c12a = (const float*)(sm + OFF_SC) + 64;
#pragma unroll
    for (int ni = 0; ni < 8; ni++)
#pragma unroll
        for (int r = 0; r < 4; r++) {
            int row = wm * 16 + g + (r >> 1) * 8;
            int col = ni * 8 + tg * 2 + (r & 1);
            int d12 = D1[ni][r] * 254 + D2[ni][r];
            cs[row * 64 + col] = s0a[col] * (float)D0[ni][r] + c12a[col] * (float)d12;
        }
    __syncthreads();

    // sequential t-scan: 512 (b, j) pairs
    const float* ba = (const float*)(sm + OFF_SC) + 128;
#pragma unroll
    for (int u = 0; u < 2; u++) {
        int pr = tid + 256 * u;
        int j = pr & 63, bl = pr >> 6;
        float bj = ba[j];
        const float* colp = cs + bl * 16 * 64 + j;
        float v = 0.0f;
        uint32_t msk = 0;
#pragma unroll
        for (int t = 0; t < 16; t++) {
            v = (v + colp[t * 64]) + bj;
            if (v >= 1.0f) { msk |= (1u << t); v -= 1.0f; }
        }
        int jj = n0 + j;
        if (jj < NOUT) {
            if (IS_LAST)
                Out[(size_t)(b0 + bl) * NOUT + jj] = (float)__popc(msk) * 0.0625f;
            else
                Mout[(size_t)(b0 + bl) * NOUT + jj] = (uint16_t)msk;
        }
    }
}

// ---------------------------------------------------------------------------
extern "C" void kernel_launch(void* const* d_in, const int* in_sizes, int n_in,
                              void* d_out, int out_size)
{
    const float* features = (const float*)d_in[0];
    const float* W1 = (const float*)d_in[1];
    const float* b1 = (const float*)d_in[2];
    const float* W2 = (const float*)d_in[3];
    const float* b2 = (const float*)d_in[4];
    const float* W3 = (const float*)d_in[5];
    const float* b3 = (const float*)d_in[6];
    const float* W4 = (const float*)d_in[7];
    const float* b4 = (const float*)d_in[8];
    float* out = (float*)d_out;

    uint16_t *m0, *m1, *m2, *m3;
    int8_t *q1, *q2, *q3, *q4;
    float *s1, *s2, *s3, *s4;
    cudaGetSymbolAddress((void**)&m0, g_M0);
    cudaGetSymbolAddress((void**)&m1, g_M1);
    cudaGetSymbolAddress((void**)&m2, g_M2);
    cudaGetSymbolAddress((void**)&m3, g_M3);
    cudaGetSymbolAddress((void**)&q1, g_Q1);
    cudaGetSymbolAddress((void**)&q2, g_Q2);
    cudaGetSymbolAddress((void**)&q3, g_Q3);
    cudaGetSymbolAddress((void**)&q4, g_Q4);
    cudaGetSymbolAddress((void**)&s1, g_S1);
    cudaGetSymbolAddress((void**)&s2, g_S2);
    cudaGetSymbolAddress((void**)&s3, g_S3);
    cudaGetSymbolAddress((void**)&s4, g_S4);

    enc_kernel<<<(BATCH * KP1 + 255) / 256, 256>>>(features);
    wsplit<<<128, 32>>>(W1, q1, s1, 128, 784, KP1);
    wsplit<<<128, 32>>>(W2, q2, s2, 128, 128, 128);
    wsplit<<<128, 32>>>(W3, q3, s3, 128, 128, 128);
    wsplit<<<784, 32>>>(W4, q4, s4, 784, 128, 128);

    constexpr int SM_L1 = 8 * KP1 * 2 + 128 * 144 + 2 * 3 * 64 * 144 + 768;
    constexpr int SM_H  = 8 * 128 * 2 + 128 * 144 + 2 * 3 * 64 * 144 + 768;

    cudaFuncSetAttribute(gemm_spike<KP1, 128, false>,
                         cudaFuncAttributeMaxDynamicSharedMemorySize, SM_L1);
    cudaFuncSetAttribute(gemm_spike<128, 128, false>,
                         cudaFuncAttributeMaxDynamicSharedMemorySize, SM_H);
    cudaFuncSetAttribute(gemm_spike<128, 784, true>,
                         cudaFuncAttributeMaxDynamicSharedMemorySize, SM_H);

    gemm_spike<KP1, 128, false>
        <<<dim3(BATCH / 8, 2), 256, SM_L1>>>(m0, q1, s1, b1, m1, nullptr);
    gemm_spike<128, 128, false>
        <<<dim3(BATCH / 8, 2), 256, SM_H>>>(m1, q2, s2, b2, m2, nullptr);
    gemm_spike<128, 128, false>
        <<<dim3(BATCH / 8, 2), 256, SM_H>>>(m2, q3, s3, b3, m3, nullptr);
    gemm_spike<128, 784, true>
        <<<dim3(BATCH / 8, 13), 256, SM_H>>>(m3, q4, s4, b4, nullptr, out);
}